// round 3
// baseline (speedup 1.0000x reference)
#include <cuda_runtime.h>

// Problem constants
#define NG    128                 // grid points per axis
#define NPTS  8192                // context points
#define G     (NG*NG)             // 16384 grid points

// Split-K config
#define S_SPLIT 64
#define CHUNK   (NPTS / S_SPLIT)  // 128
#define TJ 32
#define TK 32
#define PITCH (CHUNK + 1)         // 129, avoids bank conflicts on [j][n] layout

// Device scratch (no allocations allowed in kernel_launch)
__device__ float g_A[NG * NPTS];            // A[j][n] = exp(-0.5*(xs_j - X[n].x)^2)
__device__ float g_B[NG * NPTS];            // B[k][n] = exp(-0.5*(ys_k - X[n].y)^2)
__device__ float g_Part[S_SPLIT * 3 * G];   // split-K partial sums (12.6 MB)

// ---------------------------------------------------------------------------
// Kernel 1: separable RBF factors.
// idx plane 0 -> A (x axis, ascending), plane 1 -> B (y axis, descending).
// ---------------------------------------------------------------------------
__global__ void prep_kernel(const float* __restrict__ X) {
    int idx = blockIdx.x * blockDim.x + threadIdx.x;   // 0 .. 2*NG*NPTS-1
    int plane = idx >> 20;                             // NG*NPTS = 2^20
    int rem   = idx & ((NG * NPTS) - 1);
    int j = rem >> 13;                                 // / NPTS
    int n = rem & (NPTS - 1);

    float coord = X[n * 2 + plane];                    // plane 0: x, plane 1: y
    float gv = (plane == 0) ? (-2.0f + (4.0f / 127.0f) * (float)j)
                            : ( 2.0f - (4.0f / 127.0f) * (float)j);
    float t = gv - coord;
    float w = expf(-0.5f * t * t);

    if (plane == 0) g_A[rem] = w;
    else            g_B[rem] = w;
}

// ---------------------------------------------------------------------------
// Kernel 2: split-K contraction.
// FM[c, k, j] partial over n in [s*CHUNK, (s+1)*CHUNK):
//     w = A[j,n]*B[k,n];  acc0 += w; acc1 += w*Y[n].x; acc2 += w*Y[n].y
// grid (4, 4, S_SPLIT), block 256 threads = 16x16, each thread 2x2 outputs.
// ---------------------------------------------------------------------------
__global__ __launch_bounds__(256) void gemm_kernel(const float* __restrict__ Y) {
    __shared__ float As[TJ][PITCH];
    __shared__ float Bs[TK][PITCH];
    __shared__ float E1[CHUNK];
    __shared__ float E2[CHUNK];

    const int jt = blockIdx.x;
    const int kt = blockIdx.y;
    const int s  = blockIdx.z;
    const int tid = threadIdx.x;
    const int n0 = s * CHUNK;

    // Load A/B tiles (coalesced global reads, conflict-free smem stores)
    #pragma unroll
    for (int i = tid; i < TJ * CHUNK; i += 256) {
        int j = i >> 7;          // / CHUNK
        int n = i & (CHUNK - 1);
        As[j][n] = g_A[(jt * TJ + j) * NPTS + n0 + n];
        Bs[j][n] = g_B[(kt * TK + j) * NPTS + n0 + n];
    }
    if (tid < CHUNK) {
        float2 y = ((const float2*)Y)[n0 + tid];
        E1[tid] = y.x;
        E2[tid] = y.y;
    }
    __syncthreads();

    const int tx = tid & 15;
    const int ty = tid >> 4;

    float acc0[2][2] = {{0.f,0.f},{0.f,0.f}};
    float acc1[2][2] = {{0.f,0.f},{0.f,0.f}};
    float acc2[2][2] = {{0.f,0.f},{0.f,0.f}};

    #pragma unroll 4
    for (int n = 0; n < CHUNK; n++) {
        float e1 = E1[n];
        float e2 = E2[n];
        float a0 = As[tx * 2 + 0][n];
        float a1 = As[tx * 2 + 1][n];
        float b0 = Bs[ty * 2 + 0][n];
        float b1 = Bs[ty * 2 + 1][n];

        float w;
        w = a0 * b0; acc0[0][0] += w; acc1[0][0] = fmaf(w, e1, acc1[0][0]); acc2[0][0] = fmaf(w, e2, acc2[0][0]);
        w = a1 * b0; acc0[0][1] += w; acc1[0][1] = fmaf(w, e1, acc1[0][1]); acc2[0][1] = fmaf(w, e2, acc2[0][1]);
        w = a0 * b1; acc0[1][0] += w; acc1[1][0] = fmaf(w, e1, acc1[1][0]); acc2[1][0] = fmaf(w, e2, acc2[1][0]);
        w = a1 * b1; acc0[1][1] += w; acc1[1][1] = fmaf(w, e1, acc1[1][1]); acc2[1][1] = fmaf(w, e2, acc2[1][1]);
    }

    // Write partials (disjoint per (s, jt, kt) -> deterministic, no atomics)
    float* P = g_Part + (size_t)s * 3 * G;
    #pragma unroll
    for (int l = 0; l < 2; l++) {
        #pragma unroll
        for (int i = 0; i < 2; i++) {
            int j = jt * TJ + tx * 2 + i;
            int k = kt * TK + ty * 2 + l;
            int g = k * NG + j;
            P[0 * G + g] = acc0[l][i];
            P[1 * G + g] = acc1[l][i];
            P[2 * G + g] = acc2[l][i];
        }
    }
}

// ---------------------------------------------------------------------------
// Kernel 3: reduce splits + density normalization + channel-major layout.
// out[c*G + k*NG + j]; channels 1,2 divided by channel 0 (density).
// ---------------------------------------------------------------------------
__global__ void reduce_kernel(float* __restrict__ out) {
    int g = blockIdx.x * blockDim.x + threadIdx.x;  // 0..G-1
    float s0 = 0.f, s1 = 0.f, s2 = 0.f;
    #pragma unroll 8
    for (int s = 0; s < S_SPLIT; s++) {
        const float* P = g_Part + (size_t)s * 3 * G;
        s0 += P[0 * G + g];
        s1 += P[1 * G + g];
        s2 += P[2 * G + g];
    }
    out[0 * G + g] = s0;
    out[1 * G + g] = s1 / s0;
    out[2 * G + g] = s2 / s0;
}

// ---------------------------------------------------------------------------
extern "C" void kernel_launch(void* const* d_in, const int* in_sizes, int n_in,
                              void* d_out, int out_size) {
    const float* X = (const float*)d_in[0];   // (8192, 2)
    const float* Y = (const float*)d_in[1];   // (8192, 2)
    float* out = (float*)d_out;               // (1, 3, 128, 128)

    prep_kernel<<<(2 * NG * NPTS) / 256, 256>>>(X);
    gemm_kernel<<<dim3(NG / TJ, NG / TK, S_SPLIT), 256>>>(Y);
    reduce_kernel<<<G / 256, 256>>>(out);
}

// round 5
// speedup vs baseline: 1.4279x; 1.4279x over previous
#include <cuda_runtime.h>
#include <cstdint>

// Problem constants
#define NG    128
#define NPTS  8192
#define G     (NG*NG)

// Split config: 64 split-K slabs of KC=128, each processed in 2 sub-chunks of 64.
// Grid = (2 k-halves) x (64 splits) = 128 CTAs = one wave on 148 SMs.
#define SPL   64
#define KC    128
#define SUB   64

// Device scratch (transposed layouts: [n][j] / [n][k])
__device__ float g_At[NPTS * NG];           // A^T[n][j] = exp(-0.5*(xs_j - X[n].x)^2)
__device__ float g_Bt[NPTS * NG];           // B^T[n][k] = exp(-0.5*(ys_k - X[n].y)^2)
__device__ float g_Part[SPL * 3 * G];       // partials: [s][c][k*128 + j]

// ---------------------------------------------------------------------------
// Kernel 1: separable RBF factors, transposed output, __expf (MUFU).
// thread -> (plane, n, jq); writes float4 g_?t[n][jq*4 .. +3]. Fully coalesced.
// ---------------------------------------------------------------------------
__global__ __launch_bounds__(256) void prep_kernel(const float* __restrict__ X) {
    int t = blockIdx.x * blockDim.x + threadIdx.x;   // 0 .. 524287
    int plane = t >> 18;                             // 8192 n * 32 quads = 2^18
    int rem   = t & 0x3FFFF;
    int n  = rem >> 5;
    int jq = rem & 31;

    float coord = X[n * 2 + plane];
    float4 w;
    float* wp = &w.x;
    #pragma unroll
    for (int i = 0; i < 4; i++) {
        int j = jq * 4 + i;
        float gv = (plane == 0) ? (-2.0f + (4.0f / 127.0f) * (float)j)
                                : ( 2.0f - (4.0f / 127.0f) * (float)j);
        float d = gv - coord;
        wp[i] = __expf(-0.5f * d * d);
    }
    ((float4*)(plane ? g_Bt : g_At))[n * 32 + jq] = w;
}

// ---------------------------------------------------------------------------
// Packed fp32x2 helpers
// ---------------------------------------------------------------------------
__device__ __forceinline__ unsigned long long pk2(float lo, float hi) {
    unsigned long long r;
    asm("mov.b64 %0, {%1, %2};" : "=l"(r) : "f"(lo), "f"(hi));
    return r;
}
__device__ __forceinline__ void upk2(unsigned long long v, float& lo, float& hi) {
    asm("mov.b64 {%0, %1}, %2;" : "=f"(lo), "=f"(hi) : "l"(v));
}
__device__ __forceinline__ void fma2(unsigned long long& d,
                                     unsigned long long a, unsigned long long b) {
    asm("fma.rn.f32x2 %0, %1, %2, %0;" : "+l"(d) : "l"(a), "l"(b));
}

// ---------------------------------------------------------------------------
// Kernel 2: split-K contraction on the FMA pipe with packed f32x2.
// CTA (kh, s): for k-half kh, over n in [s*KC, (s+1)*KC):
//   Part_s[c][k][j] = sum_n A[j,n] * T_c[k,n],  T_0=B, T_1=B*y1, T_2=B*y2.
// 256 threads = 16 j-groups x 16 k-groups; thread tile: 8 j (stride 16) x 4 k x 3 c,
// accumulators packed over adjacent k pairs -> 48 packed accs.
// ---------------------------------------------------------------------------
__global__ __launch_bounds__(256, 1) void gemm_kernel(const float* __restrict__ Y) {
    extern __shared__ float smem[];
    float* As = smem;                    // [SUB][128]   32 KB
    float* Ts = smem + SUB * 128;        // [3][SUB][64] 48 KB

    const int kh  = blockIdx.x;
    const int s   = blockIdx.y;
    const int tid = threadIdx.x;
    const int jg  = tid & 15;            // j base (interleaved: j = jg + 16*i)
    const int kg  = tid >> 4;            // k group: k = kg*4 + {0..3}
    const int k0  = kg * 4;

    unsigned long long acc[8][2][3];
    #pragma unroll
    for (int i = 0; i < 8; i++)
        #pragma unroll
        for (int p = 0; p < 2; p++)
            #pragma unroll
            for (int c = 0; c < 3; c++)
                acc[i][p][c] = 0ull;

    for (int sub = 0; sub < 2; sub++) {
        const int n0 = s * KC + sub * SUB;
        __syncthreads();

        // Stage A^T rows: linear 32 KB copy (fully coalesced both sides)
        const float4* srcA = (const float4*)(g_At + n0 * 128);
        #pragma unroll
        for (int i = tid; i < SUB * 32; i += 256)
            ((float4*)As)[i] = srcA[i];

        // Stage T_c tiles: [c][n][k] for this k-half
        #pragma unroll
        for (int i = tid; i < SUB * 16; i += 256) {
            int n = i >> 4, q = i & 15;
            float4 b = *(const float4*)(g_Bt + (n0 + n) * 128 + kh * 64 + q * 4);
            float2 e = ((const float2*)Y)[n0 + n];
            *(float4*)&Ts[(0 * SUB + n) * 64 + q * 4] = b;
            *(float4*)&Ts[(1 * SUB + n) * 64 + q * 4] =
                make_float4(b.x * e.x, b.y * e.x, b.z * e.x, b.w * e.x);
            *(float4*)&Ts[(2 * SUB + n) * 64 + q * 4] =
                make_float4(b.x * e.y, b.y * e.y, b.z * e.y, b.w * e.y);
        }
        __syncthreads();

        #pragma unroll 4
        for (int n = 0; n < SUB; n++) {
            unsigned long long t2[3][2];
            #pragma unroll
            for (int c = 0; c < 3; c++)
                #pragma unroll
                for (int p = 0; p < 2; p++)
                    t2[c][p] = *(const unsigned long long*)
                               &Ts[(c * SUB + n) * 64 + k0 + p * 2];

            const float* Arow = As + n * 128 + jg;
            #pragma unroll
            for (int i = 0; i < 8; i++) {
                float a = Arow[16 * i];
                unsigned long long a2 = pk2(a, a);
                #pragma unroll
                for (int p = 0; p < 2; p++) {
                    fma2(acc[i][p][0], a2, t2[0][p]);
                    fma2(acc[i][p][1], a2, t2[1][p]);
                    fma2(acc[i][p][2], a2, t2[2][p]);
                }
            }
        }
    }

    // Epilogue: partials, layout [s][c][k*128 + j]
    float* P = g_Part + (size_t)s * 3 * G;
    #pragma unroll
    for (int i = 0; i < 8; i++) {
        int j = jg + 16 * i;
        #pragma unroll
        for (int p = 0; p < 2; p++) {
            int k = kh * 64 + k0 + p * 2;
            #pragma unroll
            for (int c = 0; c < 3; c++) {
                float lo, hi;
                upk2(acc[i][p][c], lo, hi);
                P[c * G + k * 128 + j]       = lo;
                P[c * G + (k + 1) * 128 + j] = hi;
            }
        }
    }
}

// ---------------------------------------------------------------------------
// Kernel 3: reduce splits + density normalization (layout matches out)
// ---------------------------------------------------------------------------
__global__ __launch_bounds__(256) void reduce_kernel(float* __restrict__ out) {
    int g = blockIdx.x * blockDim.x + threadIdx.x;  // 0..G-1 = k*128 + j
    float s0 = 0.f, s1 = 0.f, s2 = 0.f;
    #pragma unroll 8
    for (int s = 0; s < SPL; s++) {
        const float* P = g_Part + (size_t)s * 3 * G;
        s0 += P[0 * G + g];
        s1 += P[1 * G + g];
        s2 += P[2 * G + g];
    }
    out[0 * G + g] = s0;
    out[1 * G + g] = s1 / s0;
    out[2 * G + g] = s2 / s0;
}

// ---------------------------------------------------------------------------
extern "C" void kernel_launch(void* const* d_in, const int* in_sizes, int n_in,
                              void* d_out, int out_size) {
    const float* X = (const float*)d_in[0];
    const float* Y = (const float*)d_in[1];
    float* out = (float*)d_out;

    const int smem_bytes = (SUB * 128 + 3 * SUB * 64) * sizeof(float);  // 80 KB
    cudaFuncSetAttribute(gemm_kernel, cudaFuncAttributeMaxDynamicSharedMemorySize,
                         smem_bytes);

    prep_kernel<<<2048, 256>>>(X);
    gemm_kernel<<<dim3(2, SPL), 256, smem_bytes>>>(Y);
    reduce_kernel<<<G / 256, 256>>>(out);
}